// round 7
// baseline (speedup 1.0000x reference)
#include <cuda_runtime.h>
#include <cstdint>

#define HID 128
#define NGRAPHS 1024
#define ZD 56

// ---- graph-encoder scratch ----
__device__ float g_A   [100000 * 128];
__device__ float g_B   [100000 * 128];
__device__ float g_aggr[100000 * 128];
__device__ float g_sums[NGRAPHS * 128];
__device__ float g_cnt [NGRAPHS];
__device__ int   g_rowptr[100001];
__device__ int   g_cursor[100001];
__device__ int   g_csrsrc[400000];
__device__ int   g_bsums[128];
__device__ float g_wt  [160000];
// ---- tree-encoder scratch ----
__device__ float t_A   [20000 * 128];
__device__ float t_B   [20000 * 128];
__device__ float t_aggr[20000 * 128];
__device__ float t_sums[NGRAPHS * 128];
__device__ float t_cnt [NGRAPHS];
__device__ int   t_rowptr[20001];
__device__ int   t_cursor[20001];
__device__ int   t_csrsrc[40000];
__device__ int   t_bsums[128];
__device__ float t_wt  [160000];

#define SH_STR 132
#define SW_STR 136

__device__ __forceinline__ uint32_t f2tf32(float v) {
    uint32_t t;
    asm("cvt.rna.tf32.f32 %0, %1;" : "=r"(t) : "f"(v));
    return t;
}

__device__ __forceinline__ uint32_t smem_u32(const void* p) {
    return (uint32_t)__cvta_generic_to_shared(p);
}
__device__ __forceinline__ void cp16(uint32_t dst, const void* src) {
    asm volatile("cp.async.cg.shared.global [%0], [%1], 16;" :: "r"(dst), "l"(src));
}
__device__ __forceinline__ void cp16z(uint32_t dst, const void* src, int srcsz) {
    asm volatile("cp.async.cg.shared.global [%0], [%1], 16, %2;"
                 :: "r"(dst), "l"(src), "r"(srcsz));
}
#define CP_COMMIT() asm volatile("cp.async.commit_group;")
template<int N> __device__ __forceinline__ void cp_wait() {
    asm volatile("cp.async.wait_group %0;" :: "n"(N));
}

__device__ __forceinline__ void mma_chunk(float c[2][8][4],
                                          const uint32_t* __restrict__ sH, int k0, int hstr,
                                          const uint32_t* __restrict__ sW,
                                          int wm, int wn, int g, int tg)
{
#pragma unroll
    for (int kk = 0; kk < 32; kk += 8) {
        uint32_t a[2][4], b[8][2];
#pragma unroll
        for (int mi = 0; mi < 2; mi++) {
            int r = wm + mi * 16 + g;
            a[mi][0] = sH[r * hstr + k0 + kk + tg];
            a[mi][1] = sH[(r + 8) * hstr + k0 + kk + tg];
            a[mi][2] = sH[r * hstr + k0 + kk + tg + 4];
            a[mi][3] = sH[(r + 8) * hstr + k0 + kk + tg + 4];
        }
#pragma unroll
        for (int ni = 0; ni < 8; ni++) {
            int n = wn + ni * 8 + g;
            b[ni][0] = sW[(kk + tg) * SW_STR + n];
            b[ni][1] = sW[(kk + tg + 4) * SW_STR + n];
        }
#pragma unroll
        for (int mi = 0; mi < 2; mi++)
#pragma unroll
            for (int ni = 0; ni < 8; ni++) {
                asm volatile(
                    "mma.sync.aligned.m16n8k8.row.col.f32.tf32.tf32.f32 "
                    "{%0,%1,%2,%3},{%4,%5,%6,%7},{%8,%9},{%0,%1,%2,%3};"
                    : "+f"(c[mi][ni][0]), "+f"(c[mi][ni][1]),
                      "+f"(c[mi][ni][2]), "+f"(c[mi][ni][3])
                    : "r"(a[mi][0]), "r"(a[mi][1]), "r"(a[mi][2]), "r"(a[mi][3]),
                      "r"(b[ni][0]), "r"(b[ni][1]));
            }
    }
}

// ---------------------------------------------------------------------------
// Fused node update with cp.async weight pipeline (unchanged from R6).
// ---------------------------------------------------------------------------
__global__ __launch_bounds__(256, 2)
void fused_layer(const float* __restrict__ X, int K, int M, int xcvt,
                 const float* __restrict__ Wmain, const float* __restrict__ bmain,
                 const float* __restrict__ Wtop,  const float* __restrict__ btop,
                 const float* __restrict__ Wbot,
                 float* __restrict__ Aout, float* __restrict__ Bout)
{
    __shared__ uint32_t sH[128 * SH_STR];
    __shared__ uint32_t sW[2][32 * SW_STR];
    const int tid  = threadIdx.x;
    const int warp = tid >> 5, lane = tid & 31;
    const int g  = lane >> 2;
    const int tg = lane & 3;
    const int wm = (warp >> 1) * 32;
    const int wn = (warp & 1) * 64;
    const int row0 = blockIdx.x * 128;

    const int n1 = K >> 5;
    const int total = n1 + 8;

    auto wsrc = [&](int i) -> const float* {
        if (i < n1) return Wmain + (size_t)i * 4096;
        int j = i - n1;
        return (j < 4) ? (Wtop + (size_t)j * 4096) : (Wbot + (size_t)(j - 4) * 4096);
    };
    auto issue_w = [&](int i, int buf) {
        const float* src = wsrc(i);
        uint32_t base = smem_u32(&sW[buf][0]);
#pragma unroll
        for (int s = tid; s < 1024; s += 256) {
            int row = s >> 5, c4 = s & 31;
            cp16(base + (uint32_t)(row * SW_STR + c4 * 4) * 4, src + row * 128 + c4 * 4);
        }
    };

    if (!xcvt) {
        uint32_t base = smem_u32(sH);
        for (int s = tid; s < 128 * 32; s += 256) {
            int row = s >> 5, c4 = s & 31;
            const float* src = X + (size_t)(row0 + row) * 128 + c4 * 4;
            cp16z(base + (uint32_t)(row * SH_STR + c4 * 4) * 4, src,
                  (row0 + row < M) ? 16 : 0);
        }
    }
    issue_w(0, 0); CP_COMMIT();
    issue_w(1, 1); CP_COMMIT();
    if (xcvt) {
        int ksh = (K == 32) ? 5 : 6;
        for (int i = tid; i < 128 * K; i += 256) {
            int r = i >> ksh, k = i & (K - 1);
            int row = row0 + r;
            float v = (row < M) ? X[(size_t)row * K + k] : 0.0f;
            sH[r * SH_STR + k] = f2tf32(v);
        }
    }

    float c[2][8][4];
#pragma unroll
    for (int mi = 0; mi < 2; mi++)
#pragma unroll
        for (int ni = 0; ni < 8; ni++)
#pragma unroll
            for (int q = 0; q < 4; q++) c[mi][ni][q] = 0.0f;

    for (int i = 0; i < total; i++) {
        if (i + 2 < total) cp_wait<1>(); else cp_wait<0>();
        __syncthreads();
        int k0 = (i < n1) ? (i << 5) : (((i - n1) & 3) << 5);
        mma_chunk(c, sH, k0, SH_STR, &sW[i & 1][0], wm, wn, g, tg);
        __syncthreads();
        if (i + 2 < total) { issue_w(i + 2, i & 1); CP_COMMIT(); }

        if (i == n1 - 1) {
#pragma unroll
            for (int mi = 0; mi < 2; mi++)
#pragma unroll
                for (int half = 0; half < 2; half++) {
                    int r = wm + mi * 16 + g + half * 8;
#pragma unroll
                    for (int ni = 0; ni < 8; ni++) {
                        int col = wn + ni * 8 + tg * 2;
                        float vx = fmaxf(c[mi][ni][half * 2 + 0] + bmain[col],     0.f);
                        float vy = fmaxf(c[mi][ni][half * 2 + 1] + bmain[col + 1], 0.f);
                        sH[r * SH_STR + col]     = f2tf32(vx);
                        sH[r * SH_STR + col + 1] = f2tf32(vy);
                    }
                }
#pragma unroll
            for (int mi = 0; mi < 2; mi++)
#pragma unroll
                for (int ni = 0; ni < 8; ni++)
#pragma unroll
                    for (int q = 0; q < 4; q++) c[mi][ni][q] = 0.0f;
        } else if (i == n1 + 3) {
#pragma unroll
            for (int mi = 0; mi < 2; mi++)
#pragma unroll
                for (int half = 0; half < 2; half++) {
                    int row = row0 + wm + mi * 16 + g + half * 8;
                    if (row < M) {
#pragma unroll
                        for (int ni = 0; ni < 8; ni++) {
                            int col = wn + ni * 8 + tg * 2;
                            float2 o;
                            o.x = c[mi][ni][half * 2 + 0] + btop[col];
                            o.y = c[mi][ni][half * 2 + 1] + btop[col + 1];
                            *(float2*)(Aout + (size_t)row * 128 + col) = o;
                        }
                    }
                }
#pragma unroll
            for (int mi = 0; mi < 2; mi++)
#pragma unroll
                for (int ni = 0; ni < 8; ni++)
#pragma unroll
                    for (int q = 0; q < 4; q++) c[mi][ni][q] = 0.0f;
        } else if (i == total - 1) {
#pragma unroll
            for (int mi = 0; mi < 2; mi++)
#pragma unroll
                for (int half = 0; half < 2; half++) {
                    int row = row0 + wm + mi * 16 + g + half * 8;
                    if (row < M) {
#pragma unroll
                        for (int ni = 0; ni < 8; ni++) {
                            int col = wn + ni * 8 + tg * 2;
                            float2 o;
                            o.x = c[mi][ni][half * 2 + 0];
                            o.y = c[mi][ni][half * 2 + 1];
                            *(float2*)(Bout + (size_t)row * 128 + col) = o;
                        }
                    }
                }
        }
    }
}

// ---------------------------------------------------------------------------
// Final-layer GEMM + mean-pool epilogue, cp.async double-buffered (X and W
// are both pre-rounded tf32 -> raw copies).
// ---------------------------------------------------------------------------
__global__ __launch_bounds__(256, 2)
void gemm_pool(const float* __restrict__ X, const float* __restrict__ W,
               const float* __restrict__ bias, int M,
               const int* __restrict__ batch, float* __restrict__ sums)
{
    __shared__ uint32_t sX[2][128 * 36];
    __shared__ uint32_t sW[2][32 * SW_STR];
    const int tid  = threadIdx.x;
    const int warp = tid >> 5, lane = tid & 31;
    const int g  = lane >> 2;
    const int tg = lane & 3;
    const int wm = (warp >> 1) * 32;
    const int wn = (warp & 1) * 64;
    const int row0 = blockIdx.x * 128;

    auto issue = [&](int i, int buf) {
        uint32_t xb = smem_u32(&sX[buf][0]);
        uint32_t wb = smem_u32(&sW[buf][0]);
        const float* xs = X + (size_t)row0 * 128 + i * 32;
        const float* ws = W + (size_t)i * 4096;
#pragma unroll
        for (int s = tid; s < 1024; s += 256) {
            int row = s >> 3, c4 = s & 7;       // 128 rows x 8 c4 (32 floats)
            cp16z(xb + (uint32_t)(row * 36 + c4 * 4) * 4,
                  xs + (size_t)row * 128 + c4 * 4,
                  (row0 + row < M) ? 16 : 0);
        }
#pragma unroll
        for (int s = tid; s < 1024; s += 256) {
            int row = s >> 5, c4 = s & 31;
            cp16(wb + (uint32_t)(row * SW_STR + c4 * 4) * 4, ws + row * 128 + c4 * 4);
        }
    };

    issue(0, 0); CP_COMMIT();
    issue(1, 1); CP_COMMIT();

    float c[2][8][4];
#pragma unroll
    for (int mi = 0; mi < 2; mi++)
#pragma unroll
        for (int ni = 0; ni < 8; ni++)
#pragma unroll
            for (int q = 0; q < 4; q++) c[mi][ni][q] = 0.0f;

    for (int i = 0; i < 4; i++) {
        if (i + 2 < 4) cp_wait<1>(); else cp_wait<0>();
        __syncthreads();
        mma_chunk(c, &sX[i & 1][0], 0, 36, &sW[i & 1][0], wm, wn, g, tg);
        __syncthreads();
        if (i + 2 < 4) { issue(i + 2, i & 1); CP_COMMIT(); }
    }

#pragma unroll
    for (int mi = 0; mi < 2; mi++)
#pragma unroll
        for (int half = 0; half < 2; half++) {
            int row = row0 + wm + mi * 16 + g + half * 8;
            if (row < M) {
                int gsel = __ldg(batch + row);
#pragma unroll
                for (int ni = 0; ni < 8; ni++) {
                    int col = wn + ni * 8 + tg * 2;
                    float ox = fmaxf(c[mi][ni][half * 2 + 0] + bias[col],     0.f);
                    float oy = fmaxf(c[mi][ni][half * 2 + 1] + bias[col + 1], 0.f);
                    float* p = sums + (size_t)gsel * 128 + col;
                    asm volatile("red.global.add.v2.f32 [%0], {%1,%2};"
                                 :: "l"(p), "f"(ox), "f"(oy) : "memory");
                }
            }
        }
}

// ---------------------------------------------------------------------------
__global__ void k_cvt(const float* __restrict__ src, float* __restrict__ dst, int n)
{
    int i = blockIdx.x * blockDim.x + threadIdx.x;
    if (i < n) dst[i] = __uint_as_float(f2tf32(src[i]));
}

// ---------------------------------------------------------------------------
// CSR build
// ---------------------------------------------------------------------------
__global__ void k_count(const int* __restrict__ ei, int E, int* __restrict__ cnt)
{
    int i = blockIdx.x * blockDim.x + threadIdx.x;
    if (i < E) atomicAdd(cnt + __ldg(ei + E + i), 1);
}

__global__ void scan_block(int* __restrict__ data, int n, int* __restrict__ bsums)
{
    __shared__ int s[1024];
    int t = threadIdx.x;
    int i = blockIdx.x * 1024 + t;
    int v = (i < n) ? data[i] : 0;
    s[t] = v; __syncthreads();
    for (int d = 1; d < 1024; d <<= 1) {
        int x = (t >= d) ? s[t - d] : 0;
        __syncthreads();
        s[t] += x;
        __syncthreads();
    }
    if (i < n) data[i] = s[t] - v;
    if (t == 1023) bsums[blockIdx.x] = s[1023];
}

__global__ void scan_tops(int* __restrict__ bsums, int nb)
{
    __shared__ int s[128];
    int t = threadIdx.x;
    int v = (t < nb) ? bsums[t] : 0;
    s[t] = v; __syncthreads();
    for (int d = 1; d < 128; d <<= 1) {
        int x = (t >= d) ? s[t - d] : 0;
        __syncthreads();
        s[t] += x;
        __syncthreads();
    }
    if (t < nb) bsums[t] = s[t] - v;
}

__global__ void scan_add(int* __restrict__ data, int n,
                         const int* __restrict__ bsums, int total)
{
    int i = blockIdx.x * 1024 + threadIdx.x;
    if (i < n) data[i] += bsums[blockIdx.x];
    if (i == 0) data[n] = total;
}

__global__ void k_fill(const int* __restrict__ ei, int E,
                       int* __restrict__ cursor, int* __restrict__ csrsrc)
{
    int i = blockIdx.x * blockDim.x + threadIdx.x;
    if (i < E) {
        int d = __ldg(ei + E + i);
        int s = __ldg(ei + i);
        int p = atomicAdd(cursor + d, 1);
        csrsrc[p] = s;
    }
}

// ---------------------------------------------------------------------------
// aggr[i] = sum_e relu(A[i] + B[src_e]); 4-way unrolled edge loop (MLP=4).
// Output pre-rounded to tf32.
// ---------------------------------------------------------------------------
__global__ void csr_agg(const int* __restrict__ rowptr, const int* __restrict__ csrsrc,
                        const float* __restrict__ A, const float* __restrict__ B,
                        float* __restrict__ aggr, int n)
{
    int w = (blockIdx.x * blockDim.x + threadIdx.x) >> 5;
    int lane = threadIdx.x & 31;
    if (w >= n) return;
    int s0 = __ldg(rowptr + w), s1 = __ldg(rowptr + w + 1);
    float4 a = *(const float4*)(A + (size_t)w * 128 + lane * 4);
    float4 acc0 = make_float4(0.f, 0.f, 0.f, 0.f);
    float4 acc1 = make_float4(0.f, 0.f, 0.f, 0.f);
    float4 acc2 = make_float4(0.f, 0.f, 0.f, 0.f);
    float4 acc3 = make_float4(0.f, 0.f, 0.f, 0.f);
    int e = s0;
    for (; e + 4 <= s1; e += 4) {
        int i0 = __ldg(csrsrc + e);
        int i1 = __ldg(csrsrc + e + 1);
        int i2 = __ldg(csrsrc + e + 2);
        int i3 = __ldg(csrsrc + e + 3);
        float4 b0 = *(const float4*)(B + (size_t)i0 * 128 + lane * 4);
        float4 b1 = *(const float4*)(B + (size_t)i1 * 128 + lane * 4);
        float4 b2 = *(const float4*)(B + (size_t)i2 * 128 + lane * 4);
        float4 b3 = *(const float4*)(B + (size_t)i3 * 128 + lane * 4);
        acc0.x += fmaxf(a.x + b0.x, 0.f); acc0.y += fmaxf(a.y + b0.y, 0.f);
        acc0.z += fmaxf(a.z + b0.z, 0.f); acc0.w += fmaxf(a.w + b0.w, 0.f);
        acc1.x += fmaxf(a.x + b1.x, 0.f); acc1.y += fmaxf(a.y + b1.y, 0.f);
        acc1.z += fmaxf(a.z + b1.z, 0.f); acc1.w += fmaxf(a.w + b1.w, 0.f);
        acc2.x += fmaxf(a.x + b2.x, 0.f); acc2.y += fmaxf(a.y + b2.y, 0.f);
        acc2.z += fmaxf(a.z + b2.z, 0.f); acc2.w += fmaxf(a.w + b2.w, 0.f);
        acc3.x += fmaxf(a.x + b3.x, 0.f); acc3.y += fmaxf(a.y + b3.y, 0.f);
        acc3.z += fmaxf(a.z + b3.z, 0.f); acc3.w += fmaxf(a.w + b3.w, 0.f);
    }
    for (; e < s1; e++) {
        int s = __ldg(csrsrc + e);
        float4 b = *(const float4*)(B + (size_t)s * 128 + lane * 4);
        acc0.x += fmaxf(a.x + b.x, 0.f); acc0.y += fmaxf(a.y + b.y, 0.f);
        acc0.z += fmaxf(a.z + b.z, 0.f); acc0.w += fmaxf(a.w + b.w, 0.f);
    }
    float4 o;
    o.x = __uint_as_float(f2tf32((acc0.x + acc1.x) + (acc2.x + acc3.x)));
    o.y = __uint_as_float(f2tf32((acc0.y + acc1.y) + (acc2.y + acc3.y)));
    o.z = __uint_as_float(f2tf32((acc0.z + acc1.z) + (acc2.z + acc3.z)));
    o.w = __uint_as_float(f2tf32((acc0.w + acc1.w) + (acc2.w + acc3.w)));
    *(float4*)(aggr + (size_t)w * 128 + lane * 4) = o;
}

// ---------------------------------------------------------------------------
__global__ void pool_cnt(const int* __restrict__ batch, int n, float* __restrict__ cnt)
{
    int i = blockIdx.x * blockDim.x + threadIdx.x;
    if (i < n) atomicAdd(cnt + __ldg(batch + i), 1.0f);
}

__global__ void pool_div(const float* __restrict__ sums, const float* __restrict__ cnt,
                         float* __restrict__ fused, int colofs)
{
    int g = blockIdx.x, c = threadIdx.x;
    float cc = fmaxf(cnt[g], 1.0f);
    fused[(size_t)g * 256 + colofs + c] = sums[(size_t)g * 128 + c] / cc;
}

__global__ void head_kernel(const float* __restrict__ fused,
                            const float* __restrict__ mu_w, const float* __restrict__ mu_b,
                            const float* __restrict__ lv_w, const float* __restrict__ lv_b,
                            float* __restrict__ mu_out, float* __restrict__ lv_out)
{
    __shared__ float sf[256];
    int g = blockIdx.x, t = threadIdx.x;
    sf[t]       = fused[(size_t)g * 256 + t];
    sf[t + 128] = fused[(size_t)g * 256 + 128 + t];
    __syncthreads();
    if (t < 112) {
        bool is_mu = (t < 56);
        int j = is_mu ? t : t - 56;
        const float* Wp = is_mu ? mu_w : lv_w;
        float acc = is_mu ? mu_b[j] : lv_b[j];
#pragma unroll 8
        for (int k = 0; k < 256; k++) acc += sf[k] * Wp[k * ZD + j];
        if (is_mu) mu_out[(size_t)g * ZD + j] = acc;
        else       lv_out[(size_t)g * ZD + j] = acc;
    }
}

// ---------------------------------------------------------------------------
struct Scratch {
    float *A, *B, *aggr, *sums, *cnt, *wt;
    int *rowptr, *cursor, *csrsrc, *bsums;
};

static void csr_build(cudaStream_t st, const Scratch& S, const int* ei, int E, int n)
{
    int nb  = (n + 1023) / 1024;
    int ebk = (E + 255) / 256;
    cudaMemsetAsync(S.rowptr, 0, (size_t)(n + 1) * sizeof(int), st);
    k_count<<<ebk, 256, 0, st>>>(ei, E, S.rowptr);
    scan_block<<<nb, 1024, 0, st>>>(S.rowptr, n, S.bsums);
    scan_tops<<<1, 128, 0, st>>>(S.bsums, nb);
    scan_add<<<nb, 1024, 0, st>>>(S.rowptr, n, S.bsums, E);
    cudaMemcpyAsync(S.cursor, S.rowptr, (size_t)n * sizeof(int),
                    cudaMemcpyDeviceToDevice, st);
    k_fill<<<ebk, 256, 0, st>>>(ei, E, S.cursor, S.csrsrc);
}

static void encode_main(cudaStream_t st, const Scratch& S,
                        const float* x, int n, int din,
                        const int* batch, const float* pw, const float* pb,
                        const float* mw, const float* mb,
                        const float* lw, const float* lb,
                        float* fused, int colofs, cudaEvent_t ev_csr)
{
    int gb  = (n + 127) / 128;
    int wbk = (int)(((long long)n * 32 + 255) / 256);

    const int np = din * 128, nm = 3 * 256 * 128, nl = 3 * 128 * 128;
    float* wproj = S.wt;
    float* wmsg  = S.wt + np;
    float* wlin  = wmsg + nm;
    k_cvt<<<(np + 255) / 256, 256, 0, st>>>(pw, wproj, np);
    k_cvt<<<(nm + 255) / 256, 256, 0, st>>>(mw, wmsg, nm);
    k_cvt<<<(nl + 255) / 256, 256, 0, st>>>(lw, wlin, nl);

    fused_layer<<<gb, 256, 0, st>>>(x, din, n, 1, wproj, pb,
                                    wmsg, mb, wmsg + 16384, S.A, S.B);
    if (ev_csr) cudaStreamWaitEvent(st, ev_csr, 0);
    csr_agg<<<wbk, 256, 0, st>>>(S.rowptr, S.csrsrc, S.A, S.B, S.aggr, n);

    for (int l = 1; l < 3; l++) {
        fused_layer<<<gb, 256, 0, st>>>(S.aggr, 128, n, 0,
                                        wlin + (size_t)(l - 1) * 16384, lb + (l - 1) * 128,
                                        wmsg + (size_t)l * 32768, mb + l * 128,
                                        wmsg + (size_t)l * 32768 + 16384, S.A, S.B);
        csr_agg<<<wbk, 256, 0, st>>>(S.rowptr, S.csrsrc, S.A, S.B, S.aggr, n);
    }

    cudaMemsetAsync(S.sums, 0, (size_t)NGRAPHS * 128 * sizeof(float), st);
    gemm_pool<<<gb, 256, 0, st>>>(S.aggr, wlin + (size_t)2 * 16384, lb + 2 * 128,
                                  n, batch, S.sums);
    cudaMemsetAsync(S.cnt, 0, (size_t)NGRAPHS * sizeof(float), st);
    pool_cnt<<<(n + 255) / 256, 256, 0, st>>>(batch, n, S.cnt);
    pool_div<<<NGRAPHS, 128, 0, st>>>(S.sums, S.cnt, fused, colofs);
}

extern "C" void kernel_launch(void* const* d_in, const int* in_sizes, int n_in,
                              void* d_out, int out_size)
{
    const float* tree_x      = (const float*)d_in[0];
    const int*   tree_ei     = (const int*)  d_in[1];
    const float* graph_x     = (const float*)d_in[2];
    const int*   graph_ei    = (const int*)  d_in[3];
    const int*   batch_tree  = (const int*)  d_in[4];
    const int*   batch_graph = (const int*)  d_in[5];
    const float* t_proj_w = (const float*)d_in[6];
    const float* t_proj_b = (const float*)d_in[7];
    const float* t_msg_w  = (const float*)d_in[8];
    const float* t_msg_b  = (const float*)d_in[9];
    const float* t_lin_w  = (const float*)d_in[10];
    const float* t_lin_b  = (const float*)d_in[11];
    const float* gr_proj_w = (const float*)d_in[12];
    const float* gr_proj_b = (const float*)d_in[13];
    const float* gr_msg_w  = (const float*)d_in[14];
    const float* gr_msg_b  = (const float*)d_in[15];
    const float* gr_lin_w  = (const float*)d_in[16];
    const float* gr_lin_b  = (const float*)d_in[17];
    const float* mu_w = (const float*)d_in[18];
    const float* mu_b = (const float*)d_in[19];
    const float* lv_w = (const float*)d_in[20];
    const float* lv_b = (const float*)d_in[21];
    float* out = (float*)d_out;

    const int n_tree  = in_sizes[0] / 64;
    const int e_tree  = in_sizes[1] / 2;
    const int n_graph = in_sizes[2] / 32;
    const int e_graph = in_sizes[3] / 2;

    Scratch G, T;
    cudaGetSymbolAddress((void**)&G.A,      g_A);
    cudaGetSymbolAddress((void**)&G.B,      g_B);
    cudaGetSymbolAddress((void**)&G.aggr,   g_aggr);
    cudaGetSymbolAddress((void**)&G.sums,   g_sums);
    cudaGetSymbolAddress((void**)&G.cnt,    g_cnt);
    cudaGetSymbolAddress((void**)&G.wt,     g_wt);
    cudaGetSymbolAddress((void**)&G.rowptr, g_rowptr);
    cudaGetSymbolAddress((void**)&G.cursor, g_cursor);
    cudaGetSymbolAddress((void**)&G.csrsrc, g_csrsrc);
    cudaGetSymbolAddress((void**)&G.bsums,  g_bsums);
    cudaGetSymbolAddress((void**)&T.A,      t_A);
    cudaGetSymbolAddress((void**)&T.B,      t_B);
    cudaGetSymbolAddress((void**)&T.aggr,   t_aggr);
    cudaGetSymbolAddress((void**)&T.sums,   t_sums);
    cudaGetSymbolAddress((void**)&T.cnt,    t_cnt);
    cudaGetSymbolAddress((void**)&T.wt,     t_wt);
    cudaGetSymbolAddress((void**)&T.rowptr, t_rowptr);
    cudaGetSymbolAddress((void**)&T.cursor, t_cursor);
    cudaGetSymbolAddress((void**)&T.csrsrc, t_csrsrc);
    cudaGetSymbolAddress((void**)&T.bsums,  t_bsums);

    static cudaStream_t s_tree = nullptr, s_csr = nullptr;
    static cudaEvent_t ev_fork = nullptr, ev_join = nullptr, ev_csr = nullptr;
    if (!s_tree) {
        cudaStreamCreateWithFlags(&s_tree, cudaStreamNonBlocking);
        cudaStreamCreateWithFlags(&s_csr, cudaStreamNonBlocking);
        cudaEventCreateWithFlags(&ev_fork, cudaEventDisableTiming);
        cudaEventCreateWithFlags(&ev_join, cudaEventDisableTiming);
        cudaEventCreateWithFlags(&ev_csr, cudaEventDisableTiming);
    }

    float* fused = out + 2 * NGRAPHS * ZD;   // output layout: mu | logvar | fused

    // Fork: tree encoder on s_tree, graph CSR on s_csr, graph GEMMs on main.
    cudaEventRecord(ev_fork, 0);
    cudaStreamWaitEvent(s_tree, ev_fork, 0);
    cudaStreamWaitEvent(s_csr, ev_fork, 0);

    // Tree: CSR build + encoder, all on s_tree (hidden under graph work).
    csr_build(s_tree, T, tree_ei, e_tree, n_tree);
    encode_main(s_tree, T, tree_x, n_tree, 64, batch_tree,
                t_proj_w, t_proj_b, t_msg_w, t_msg_b, t_lin_w, t_lin_b,
                fused, 0, nullptr);

    // Graph: CSR build overlapped with layer-0 GEMM.
    csr_build(s_csr, G, graph_ei, e_graph, n_graph);
    cudaEventRecord(ev_csr, s_csr);
    encode_main(0, G, graph_x, n_graph, 32, batch_graph,
                gr_proj_w, gr_proj_b, gr_msg_w, gr_msg_b, gr_lin_w, gr_lin_b,
                fused, 128, ev_csr);

    cudaEventRecord(ev_join, s_tree);
    cudaStreamWaitEvent(0, ev_join, 0);

    head_kernel<<<NGRAPHS, 128>>>(fused, mu_w, mu_b, lv_w, lv_b,
                                  out, out + NGRAPHS * ZD);
}